// round 15
// baseline (speedup 1.0000x reference)
#include <cuda_runtime.h>
#include <cuda_fp16.h>
#include <math.h>

#define DIM    3072
#define HEADS  48
#define HD     64
#define TEMB_D 512
#define BATCH  2
#define T_TXT  226
#define S_VID  1024
#define S_TOT  1250
#define FF_D   12288
#define M_ROWS 2500      // BATCH * S_TOT
#define MODSZ  18432     // 6*DIM
#define BIGN   7680000   // M_ROWS*DIM
#define QKV_N  9216      // 3*DIM
#define VT_STRIDE 1280   // padded key stride for V^T (16B-aligned cp.async)

// ---------------- scratch (static device memory; no allocs) ----------------
__device__ float g_silu[BATCH * TEMB_D];
__device__ float g_mods1[BATCH * MODSZ];
__device__ float g_mods2[BATCH * MODSZ];
__device__ float g_dummyf[2];
__device__ __half g_cat[BIGN];          // cat1/cat2 (fp16)
__device__ __half g_qkvh[(size_t)M_ROWS * QKV_N];  // fused qkv out (fp16)
__device__ __half g_q[BIGN];            // (B,H,S,HD) scaled fp16
__device__ __half g_k[BIGN];            // fp16
__device__ __half g_vT[BATCH * HEADS * HD * VT_STRIDE];  // fp16
__device__ __half g_attn[BIGN];         // attention out (fp16)
__device__ __half g_ff1[M_ROWS * FF_D]; // (fp16)

// fp16 weight copies
__device__ __half g_wqkv[3 * DIM * DIM];   // rows: wq | wk | wv
__device__ __half g_wo[DIM * DIM];
__device__ __half g_wf1[FF_D * DIM];
__device__ __half g_wf2[FF_D * DIM];

template<int ID> __device__ __forceinline__ __half* hbuf();
template<> __device__ __forceinline__ __half* hbuf<0>() { return g_cat; }
template<> __device__ __forceinline__ __half* hbuf<1>() { return g_attn; }
template<> __device__ __forceinline__ __half* hbuf<2>() { return g_ff1; }
template<> __device__ __forceinline__ __half* hbuf<3>() { return g_qkvh; }

template<int ID> __device__ __forceinline__ float* fbuf();
template<> __device__ __forceinline__ float* fbuf<0>() { return g_dummyf; }
template<> __device__ __forceinline__ float* fbuf<3>() { return g_dummyf; }

template<int ID> __device__ __forceinline__ __half* whbuf();
template<> __device__ __forceinline__ __half* whbuf<0>() { return g_wqkv; }
template<> __device__ __forceinline__ __half* whbuf<1>() { return g_wo; }
template<> __device__ __forceinline__ __half* whbuf<2>() { return g_wf1; }
template<> __device__ __forceinline__ __half* whbuf<3>() { return g_wf2; }

__device__ __forceinline__ float gelu_tanh(float x) {
    float t = tanhf(0.7978845608028654f * (x + 0.044715f * x * x * x));
    return 0.5f * x * (1.0f + t);
}
__device__ __forceinline__ unsigned smem_u32(const void* p) {
    return (unsigned)__cvta_generic_to_shared(p);
}
__device__ __forceinline__ void cp_async16(unsigned dst, const void* src) {
    asm volatile("cp.async.cg.shared.global [%0], [%1], 16;" :: "r"(dst), "l"(src));
}
#define CP_COMMIT() asm volatile("cp.async.commit_group;" ::: "memory")
#define CP_WAIT1()  asm volatile("cp.async.wait_group 1;" ::: "memory")
#define CP_WAIT0()  asm volatile("cp.async.wait_group 0;" ::: "memory")

__device__ __forceinline__ void mma_f16(float* d, const unsigned* a, const unsigned* b) {
    asm volatile(
        "mma.sync.aligned.m16n8k16.row.col.f32.f16.f16.f32 "
        "{%0,%1,%2,%3},{%4,%5,%6,%7},{%8,%9},{%0,%1,%2,%3};"
        : "+f"(d[0]), "+f"(d[1]), "+f"(d[2]), "+f"(d[3])
        : "r"(a[0]), "r"(a[1]), "r"(a[2]), "r"(a[3]), "r"(b[0]), "r"(b[1]));
}

// ---------------- fp16 weight copy ----------------
template<int WID>
__global__ void h_copy(const float* __restrict__ src, int dst_off, int n8) {
    int i = blockIdx.x * blockDim.x + threadIdx.x;
    if (i >= n8) return;
    float4 v0 = ((const float4*)src)[2 * i];
    float4 v1 = ((const float4*)src)[2 * i + 1];
    __half2 h0 = __floats2half2_rn(v0.x, v0.y);
    __half2 h1 = __floats2half2_rn(v0.z, v0.w);
    __half2 h2 = __floats2half2_rn(v1.x, v1.y);
    __half2 h3 = __floats2half2_rn(v1.z, v1.w);
    uint4 out;
    out.x = *(unsigned*)&h0; out.y = *(unsigned*)&h1;
    out.z = *(unsigned*)&h2; out.w = *(unsigned*)&h3;
    ((uint4*)(whbuf<WID>() + dst_off))[i] = out;
}

// ---------------- silu(temb) ----------------
__global__ void silu_kernel(const float* __restrict__ temb) {
    int i = blockIdx.x * blockDim.x + threadIdx.x;
    if (i < BATCH * TEMB_D) {
        float x = temb[i];
        g_silu[i] = x / (1.0f + expf(-x));
    }
}

// ---------------- mods = silu(temb) @ W.T + b ----------------
template<int WHICH>
__global__ void mods_kernel(const float* __restrict__ w, const float* __restrict__ bias) {
    float* out = (WHICH == 0) ? g_mods1 : g_mods2;
    int gw = (blockIdx.x * blockDim.x + threadIdx.x) >> 5;
    int lane = threadIdx.x & 31;
    if (gw >= BATCH * MODSZ) return;
    int b = gw / MODSZ, n = gw % MODSZ;
    const float* wr = w + (size_t)n * TEMB_D;
    const float* sr = g_silu + b * TEMB_D;
    float acc = 0.f;
    #pragma unroll 4
    for (int k = lane; k < TEMB_D; k += 32) acc += wr[k] * sr[k];
    #pragma unroll
    for (int off = 16; off; off >>= 1) acc += __shfl_xor_sync(0xffffffffu, acc, off);
    if (lane == 0) out[gw] = acc + bias[n];
}

// ---------------- LayerNorm + adaLN modulation -> g_cat (fp16) ----------------
template<int WHICH>
__global__ __launch_bounds__(256) void ln_mod_kernel(
    const float* __restrict__ hid, const float* __restrict__ enc,
    const float* __restrict__ gamma, const float* __restrict__ beta) {
    const float* mods = (WHICH == 0) ? g_mods1 : g_mods2;
    int row = blockIdx.x;
    int b = row / S_TOT, s = row % S_TOT;
    const float* src;
    int sh_off;
    if (s < T_TXT) { src = enc + ((size_t)b * T_TXT + s) * DIM; sh_off = 3 * DIM; }
    else           { src = hid + ((size_t)b * S_VID + (s - T_TXT)) * DIM; sh_off = 0; }
    const float* mrow = mods + (size_t)b * MODSZ;
    __shared__ float ws[8], wq[8], stat[2];
    int tid = threadIdx.x;
    int lane = tid & 31, warp = tid >> 5;
    float4 xv[3];
    float sum = 0.f, sq = 0.f;
    #pragma unroll
    for (int c = 0; c < 3; c++) {
        xv[c] = *(const float4*)(src + c * 1024 + tid * 4);
        sum += xv[c].x + xv[c].y + xv[c].z + xv[c].w;
        sq  += xv[c].x * xv[c].x + xv[c].y * xv[c].y
             + xv[c].z * xv[c].z + xv[c].w * xv[c].w;
    }
    #pragma unroll
    for (int off = 16; off; off >>= 1) {
        sum += __shfl_xor_sync(0xffffffffu, sum, off);
        sq  += __shfl_xor_sync(0xffffffffu, sq, off);
    }
    if (lane == 0) { ws[warp] = sum; wq[warp] = sq; }
    __syncthreads();
    if (tid == 0) {
        float ts = 0.f, tq = 0.f;
        #pragma unroll
        for (int i = 0; i < 8; i++) { ts += ws[i]; tq += wq[i]; }
        float mean = ts * (1.f / DIM);
        float var = tq * (1.f / DIM) - mean * mean;
        stat[0] = mean;
        stat[1] = rsqrtf(var + 1e-5f);
    }
    __syncthreads();
    float mean = stat[0], inv = stat[1];
    __half* orow = g_cat + (size_t)row * DIM;
    #pragma unroll
    for (int c = 0; c < 3; c++) {
        int d = c * 1024 + tid * 4;
        float4 gm = *(const float4*)(gamma + d);
        float4 bt = *(const float4*)(beta + d);
        float4 sc = *(const float4*)(mrow + sh_off + DIM + d);
        float4 sh = *(const float4*)(mrow + sh_off + d);
        float y0 = ((xv[c].x - mean) * inv * gm.x + bt.x) * (1.f + sc.x) + sh.x;
        float y1 = ((xv[c].y - mean) * inv * gm.y + bt.y) * (1.f + sc.y) + sh.y;
        float y2 = ((xv[c].z - mean) * inv * gm.z + bt.z) * (1.f + sc.z) + sh.z;
        float y3 = ((xv[c].w - mean) * inv * gm.w + bt.w) * (1.f + sc.w) + sh.w;
        __half2 h01 = __floats2half2_rn(y0, y1);
        __half2 h23 = __floats2half2_rn(y2, y3);
        uint2 pk;
        pk.x = *(unsigned*)&h01; pk.y = *(unsigned*)&h23;
        *(uint2*)(orow + d) = pk;
    }
}

// ======== FP16 GEMM NT, 128x128 CTA, 4 warps of 64x64, BK=32, 2-stage cp.async ========
// EPI=0: plain write. EPI=1: fused resid. EPI=2: fused final_add.
template<int ACT, int SRC, int BID, int DST, int OUTH, int EPI>
__global__ __launch_bounds__(128, 2) void hgemm_nt(
    const float* __restrict__ bias, int b_off, int M, int N, int K,
    const float* __restrict__ hid, const float* __restrict__ enc,
    float* __restrict__ out_h, float* __restrict__ out_e) {
    const __half* A = hbuf<SRC>();
    const __half* Bw = whbuf<BID>() + b_off;
    __shared__ __align__(16) __half As[2][128][40];
    __shared__ __align__(16) __half Bs[2][128][40];
    const int bm = blockIdx.y * 128;
    const int bn = blockIdx.x * 128;
    const int tid = threadIdx.x;
    const int lane = tid & 31;
    const int w = tid >> 5;
    const int wm = (w & 1) * 64;
    const int wn = (w >> 1) * 64;
    const int g = lane >> 2;
    const int t = lane & 3;

    float acc[4][8][4];
    #pragma unroll
    for (int mf = 0; mf < 4; mf++)
        #pragma unroll
        for (int nf = 0; nf < 8; nf++)
            #pragma unroll
            for (int i = 0; i < 4; i++) acc[mf][nf][i] = 0.f;

    const int nch = K >> 5;

#define FILL(j)                                                                 \
    {                                                                           \
        int st_ = (j) & 1;                                                      \
        int k0_ = (j) << 5;                                                     \
        _Pragma("unroll")                                                       \
        for (int i_ = 0; i_ < 4; i_++) {                                        \
            int idx_ = i_ * 128 + tid;                                          \
            int row_ = idx_ >> 2;                                               \
            int c8_ = (idx_ & 3) << 3;                                          \
            int ga_ = bm + row_; if (ga_ >= M) ga_ = M - 1;                     \
            cp_async16(smem_u32(&As[st_][row_][c8_]),                           \
                       A + (size_t)ga_ * K + k0_ + c8_);                        \
            cp_async16(smem_u32(&Bs[st_][row_][c8_]),                           \
                       Bw + (size_t)(bn + row_) * K + k0_ + c8_);               \
        }                                                                       \
        CP_COMMIT();                                                            \
    }

    FILL(0);

    for (int j = 0; j < nch; j++) {
        if (j + 1 < nch) { FILL(j + 1); CP_WAIT1(); } else { CP_WAIT0(); }
        __syncthreads();
        int st = j & 1;
        #pragma unroll
        for (int kk = 0; kk < 32; kk += 16) {
            unsigned af[4][4], bf[8][2];
            #pragma unroll
            for (int mf = 0; mf < 4; mf++) {
                int rb = wm + mf * 16;
                af[mf][0] = *(const unsigned*)&As[st][rb + g][kk + 2 * t];
                af[mf][1] = *(const unsigned*)&As[st][rb + g + 8][kk + 2 * t];
                af[mf][2] = *(const unsigned*)&As[st][rb + g][kk + 2 * t + 8];
                af[mf][3] = *(const unsigned*)&As[st][rb + g + 8][kk + 2 * t + 8];
            }
            #pragma unroll
            for (int nf = 0; nf < 8; nf++) {
                int cb = wn + nf * 8;
                bf[nf][0] = *(const unsigned*)&Bs[st][cb + g][kk + 2 * t];
                bf[nf][1] = *(const unsigned*)&Bs[st][cb + g][kk + 2 * t + 8];
            }
            #pragma unroll
            for (int mf = 0; mf < 4; mf++)
                #pragma unroll
                for (int nf = 0; nf < 8; nf++)
                    mma_f16(acc[mf][nf], af[mf], bf[nf]);
        }
        __syncthreads();
    }
#undef FILL

    // epilogue
    const float* mods = (EPI == 1) ? g_mods1 : g_mods2;
    #pragma unroll
    for (int mf = 0; mf < 4; mf++) {
        int r0 = bm + wm + mf * 16 + g;
        int r1 = r0 + 8;
        int b0r = 0, s0r = 0, b1r = 0, s1r = 0;
        if (EPI >= 1) {
            b0r = r0 / S_TOT; s0r = r0 % S_TOT;
            b1r = r1 / S_TOT; s1r = r1 % S_TOT;
        }
        #pragma unroll
        for (int nf = 0; nf < 8; nf++) {
            int col = bn + wn + nf * 8 + 2 * t;
            float bb0 = bias ? bias[col] : 0.f;
            float bb1 = bias ? bias[col + 1] : 0.f;
            float v0 = acc[mf][nf][0] + bb0;
            float v1 = acc[mf][nf][1] + bb1;
            float v2 = acc[mf][nf][2] + bb0;
            float v3 = acc[mf][nf][3] + bb1;
            if (ACT == 1) {
                v0 = gelu_tanh(v0); v1 = gelu_tanh(v1);
                v2 = gelu_tanh(v2); v3 = gelu_tanh(v3);
            }
            if (EPI == 0) {
                if (OUTH == 1) {
                    __half* C = hbuf<DST>();
                    __half2 h01 = __floats2half2_rn(v0, v1);
                    __half2 h23 = __floats2half2_rn(v2, v3);
                    if (r0 < M) *(__half2*)(C + (size_t)r0 * N + col) = h01;
                    if (r1 < M) *(__half2*)(C + (size_t)r1 * N + col) = h23;
                } else {
                    float* C = fbuf<DST>();
                    if (r0 < M) *(float2*)(C + (size_t)r0 * N + col) = make_float2(v0, v1);
                    if (r1 < M) *(float2*)(C + (size_t)r1 * N + col) = make_float2(v2, v3);
                }
            } else {
                #pragma unroll
                for (int half = 0; half < 2; half++) {
                    int r = half ? r1 : r0;
                    if (r >= M) continue;
                    int bb = half ? b1r : b0r;
                    int ss = half ? s1r : s0r;
                    float va = half ? v2 : v0;
                    float vb = half ? v3 : v1;
                    if (ss < T_TXT) {
                        float ga = mods[bb * MODSZ + 5 * DIM + col];
                        float gb = mods[bb * MODSZ + 5 * DIM + col + 1];
                        size_t idx = ((size_t)bb * T_TXT + ss) * DIM + col;
                        if (EPI == 1) {
                            float2 e = *(const float2*)(enc + idx);
                            *(float2*)(out_e + idx) = make_float2(e.x + ga * va, e.y + gb * vb);
                        } else {
                            float2 e = *(const float2*)(out_e + idx);
                            *(float2*)(out_e + idx) = make_float2(e.x + ga * va, e.y + gb * vb);
                        }
                    } else {
                        float ga = mods[bb * MODSZ + 2 * DIM + col];
                        float gb = mods[bb * MODSZ + 2 * DIM + col + 1];
                        size_t idx = ((size_t)bb * S_VID + (ss - T_TXT)) * DIM + col;
                        if (EPI == 1) {
                            float2 hh = *(const float2*)(hid + idx);
                            *(float2*)(out_h + idx) = make_float2(hh.x + ga * va, hh.y + gb * vb);
                        } else {
                            float2 hh = *(const float2*)(out_h + idx);
                            *(float2*)(out_h + idx) = make_float2(hh.x + ga * va, hh.y + gb * vb);
                        }
                    }
                }
            }
        }
    }
}

// ---------------- v transpose: g_qkvh v-section fp16 -> (B,H,HD,S) fp16 ----------------
__global__ __launch_bounds__(128) void vtrans_kernel() {
    __shared__ __half tl[64][72];
    int bh = blockIdx.y;
    int stile = blockIdx.x;
    int b = bh / HEADS, h = bh % HEADS;
    int tid = threadIdx.x;
    int s0 = stile * 64;
    #pragma unroll
    for (int i = 0; i < 4; i++) {
        int idx = i * 128 + tid;
        int r = idx >> 3, c8 = (idx & 7) << 3;
        int s = s0 + r;
        if (s >= S_TOT) s = S_TOT - 1;
        uint4 v = *(const uint4*)(g_qkvh + ((size_t)(b * S_TOT + s)) * QKV_N
                                  + 2 * DIM + h * HD + c8);
        *(uint4*)&tl[r][c8] = v;
    }
    __syncthreads();
    __half* dst = g_vT + (size_t)bh * HD * VT_STRIDE;
    #pragma unroll
    for (int i = 0; i < 16; i++) {
        int idx = i * 128 + tid;
        int d = idx >> 5;
        int sc = (idx & 31) << 1;
        int s = s0 + sc;
        if (s + 1 < S_TOT) {
            __half2 p;
            p.x = tl[sc][d]; p.y = tl[sc + 1][d];
            *(__half2*)(dst + (size_t)d * VT_STRIDE + s) = p;
        } else if (s < S_TOT) {
            dst[(size_t)d * VT_STRIDE + s] = tl[sc][d];
        }
    }
}

// ---------------- per-head QK LayerNorm + RoPE -> fp16 (q scaled by 1/8) ----------------
__global__ __launch_bounds__(128) void qk_post_kernel(
    const float* __restrict__ rope_cos, const float* __restrict__ rope_sin,
    const float* __restrict__ nqg, const float* __restrict__ nqb,
    const float* __restrict__ nkg, const float* __restrict__ nkb) {
    int gw = (blockIdx.x * 128 + threadIdx.x) >> 5;
    int lane = threadIdx.x & 31;
    if (gw >= BATCH * HEADS * S_TOT) return;
    int b = gw / (HEADS * S_TOT);
    int rem = gw % (HEADS * S_TOT);
    int h = rem / S_TOT, s = rem % S_TOT;
    size_t base_off = ((size_t)(b * S_TOT + s)) * QKV_N + h * HD + lane * 2;
    size_t dst_off = (size_t)gw * HD + lane * 2;
    float c0 = 1.f, s0 = 0.f, c1 = 1.f, s1 = 0.f;
    bool do_rope = (s >= T_TXT);
    if (do_rope) {
        int i = s - T_TXT;
        c0 = rope_cos[i * HD + lane * 2];     s0 = rope_sin[i * HD + lane * 2];
        c1 = rope_cos[i * HD + lane * 2 + 1]; s1 = rope_sin[i * HD + lane * 2 + 1];
    }
    #pragma unroll
    for (int which = 0; which < 2; which++) {
        const __half* src = g_qkvh + which * DIM;
        __half* dst = (which == 0) ? g_q : g_k;
        const float* gg = (which == 0) ? nqg : nkg;
        const float* bb = (which == 0) ? nqb : nkb;
        float2 x = __half22float2(*(const __half2*)(src + base_off));
        float sum = x.x + x.y;
        float sq = x.x * x.x + x.y * x.y;
        #pragma unroll
        for (int off = 16; off; off >>= 1) {
            sum += __shfl_xor_sync(0xffffffffu, sum, off);
            sq  += __shfl_xor_sync(0xffffffffu, sq, off);
        }
        float mean = sum * (1.f / HD);
        float var = sq * (1.f / HD) - mean * mean;
        float inv = rsqrtf(var + 1e-6f);
        float y0 = (x.x - mean) * inv * gg[2 * lane]     + bb[2 * lane];
        float y1 = (x.y - mean) * inv * gg[2 * lane + 1] + bb[2 * lane + 1];
        if (do_rope) {
            float r0 = y0 * c0 - y1 * s0;
            float r1 = y1 * c1 + y0 * s1;
            y0 = r0; y1 = r1;
        }
        if (which == 0) { y0 *= 0.125f; y1 *= 0.125f; }
        *(__half2*)(dst + dst_off) = __floats2half2_rn(y0, y1);
    }
}

// ---------------- fp16 tensor-core flash attention, 128-row q tile ----------------
// 256 threads, 8 warps x (16 rows x 64 keys); K/V double-buffered 64-key tiles.
#define HST 72
#define ATT_SMEM ((128 + 4 * 64) * HST * 2)   // 55296 B

__global__ __launch_bounds__(256, 2) void attn_kernel() {
    extern __shared__ __half hsm[];
    __half (*QPs)[HST] = (__half(*)[HST])hsm;                   // [128][HST]
    __half (*Ksm)[HST] = (__half(*)[HST])(hsm + 128 * HST);     // [2*64][HST]
    __half (*Vsm)[HST] = (__half(*)[HST])(hsm + (128 + 128) * HST);
    const int qt = blockIdx.x;     // 0..9
    const int bh = blockIdx.y;     // 0..95
    const int b = bh / HEADS, h = bh % HEADS;
    const __half* Qb = g_q + (size_t)bh * S_TOT * HD;
    const __half* Kb = g_k + (size_t)bh * S_TOT * HD;
    const __half* Vb = g_vT + (size_t)bh * HD * VT_STRIDE;
    const int tid = threadIdx.x;
    const int w = tid >> 5, lane = tid & 31;
    const int g = lane >> 2, t = lane & 3;
    const int w16 = w * 16;        // 0..112
    const int NKT = (S_TOT + 63) / 64;
    const int LASTV = S_TOT - (NKT - 1) * 64;

    // Q fill: 128 rows x 64 halves = 1024 16B-chunks over 256 threads
    #pragma unroll
    for (int i = 0; i < 4; i++) {
        int idx = i * 256 + tid;
        int r = idx >> 3, c8 = (idx & 7) << 3;
        int qr = qt * 128 + r; if (qr >= S_TOT) qr = S_TOT - 1;
        cp_async16(smem_u32(&QPs[r][c8]), Qb + (size_t)qr * HD + c8);
    }
    CP_COMMIT();

#define AFILL(kt_)                                                                \
    {                                                                             \
        int st_ = (kt_) & 1;                                                      \
        _Pragma("unroll")                                                         \
        for (int i_ = 0; i_ < 2; i_++) {                                          \
            int idx_ = i_ * 256 + tid;                                            \
            int r_ = idx_ >> 3, c8_ = (idx_ & 7) << 3;                            \
            int key_ = (kt_) * 64 + r_; if (key_ >= S_TOT) key_ = S_TOT - 1;      \
            cp_async16(smem_u32(&Ksm[st_ * 64 + r_][c8_]),                        \
                       Kb + (size_t)key_ * HD + c8_);                             \
            cp_async16(smem_u32(&Vsm[st_ * 64 + r_][c8_]),                        \
                       Vb + (size_t)r_ * VT_STRIDE + (kt_) * 64 + c8_);           \
        }                                                                         \
        CP_COMMIT();                                                              \
    }

    AFILL(0);

    unsigned qf[4][4];
    float o[8][4];
    #pragma unroll
    for (int nf = 0; nf < 8; nf++)
        #pragma unroll
        for (int i = 0; i < 4; i++) o[nf][i] = 0.f;
    float m0 = -1e30f, m1 = -1e30f, l0 = 0.f, l1 = 0.f;

    for (int kt = 0; kt < NKT; kt++) {
        if (kt + 1 < NKT) { AFILL(kt + 1); CP_WAIT1(); } else { CP_WAIT0(); }
        __syncthreads();
        if (kt == 0) {
            #pragma unroll
            for (int ks = 0; ks < 4; ks++) {
                qf[ks][0] = *(const unsigned*)&QPs[w16 + g][ks * 16 + 2 * t];
                qf[ks][1] = *(const unsigned*)&QPs[w16 + g + 8][ks * 16 + 2 * t];
                qf[ks][2] = *(const unsigned*)&QPs[w16 + g][ks * 16 + 2 * t + 8];
                qf[ks][3] = *(const unsigned*)&QPs[w16 + g + 8][ks * 16 + 2 * t + 8];
            }
            __syncthreads();   // all Q reads done before P overwrites
        }
        const __half (*Kst)[HST] = Ksm + (kt & 1) * 64;
        const __half (*Vst)[HST] = Vsm + (kt & 1) * 64;

        float s[8][4];
        #pragma unroll
        for (int nf = 0; nf < 8; nf++)
            #pragma unroll
            for (int i = 0; i < 4; i++) s[nf][i] = 0.f;
        #pragma unroll
        for (int ks = 0; ks < 4; ks++) {
            #pragma unroll
            for (int nf = 0; nf < 8; nf++) {
                unsigned bfr[2];
                bfr[0] = *(const unsigned*)&Kst[nf * 8 + g][ks * 16 + 2 * t];
                bfr[1] = *(const unsigned*)&Kst[nf * 8 + g][ks * 16 + 2 * t + 8];
                mma_f16(s[nf], qf[ks], bfr);
            }
        }
        if (kt == NKT - 1) {
            #pragma unroll
            for (int nf = 0; nf < 8; nf++) {
                int c0 = nf * 8 + 2 * t;
                if (c0 >= LASTV)     { s[nf][0] = -1e30f; s[nf][2] = -1e30f; }
                if (c0 + 1 >= LASTV) { s[nf][1] = -1e30f; s[nf][3] = -1e30f; }
            }
        }
        float tm0 = -1e30f, tm1 = -1e30f;
        #pragma unroll
        for (int nf = 0; nf < 8; nf++) {
            tm0 = fmaxf(tm0, fmaxf(s[nf][0], s[nf][1]));
            tm1 = fmaxf(tm1, fmaxf(s[nf][2], s[nf][3]));
        }
        tm0 = fmaxf(tm0, __shfl_xor_sync(0xffffffffu, tm0, 1));
        tm0 = fmaxf(tm0, __shfl_xor_sync(0xffffffffu, tm0, 2));
        tm1 = fmaxf(tm1, __shfl_xor_sync(0xffffffffu, tm1, 1));
        tm1 = fmaxf(tm1, __shfl_xor_sync(0xffffffffu, tm1, 2));
        float mn0 = fmaxf(m0, tm0), mn1 = fmaxf(m1, tm1);
        float sc0 = __expf(m0 - mn0), sc1 = __expf(m1 - mn1);
        float ls0 = 0.f, ls1 = 0.f;
        #pragma unroll
        for (int nf = 0; nf < 8; nf++) {
            float p0 = __expf(s[nf][0] - mn0);
            float p1 = __expf(s[nf][1] - mn0);
            float p2 = __expf(s[nf][2] - mn1);
            float p3 = __expf(s[nf][3] - mn1);
            __half2 h01 = __floats2half2_rn(p0, p1);
            __half2 h23 = __floats2half2_rn(p2, p3);
            float2 f01 = __half22float2(h01);
            float2 f23 = __half22float2(h23);
            ls0 += f01.x + f01.y; ls1 += f23.x + f23.y;
            *(__half2*)&QPs[w16 + g][nf * 8 + 2 * t]     = h01;
            *(__half2*)&QPs[w16 + g + 8][nf * 8 + 2 * t] = h23;
        }
        l0 = l0 * sc0 + ls0;
        l1 = l1 * sc1 + ls1;
        m0 = mn0; m1 = mn1;
        #pragma unroll
        for (int nf = 0; nf < 8; nf++) {
            o[nf][0] *= sc0; o[nf][1] *= sc0;
            o[nf][2] *= sc1; o[nf][3] *= sc1;
        }
        __syncwarp();
        #pragma unroll
        for (int ks = 0; ks < 4; ks++) {
            unsigned pf[4];
            pf[0] = *(const unsigned*)&QPs[w16 + g][ks * 16 + 2 * t];
            pf[1] = *(const unsigned*)&QPs[w16 + g + 8][ks * 16 + 2 * t];
            pf[2] = *(const unsigned*)&QPs[w16 + g][ks * 16 + 2 * t + 8];
            pf[3] = *(const unsigned*)&QPs[w16 + g + 8][ks * 16 + 2 * t + 8];
            #pragma unroll
            for (int nf = 0; nf < 8; nf++) {
                unsigned vf[2];
                vf[0] = *(const unsigned*)&Vst[nf * 8 + g][ks * 16 + 2 * t];
                vf[1] = *(const unsigned*)&Vst[nf * 8 + g][ks * 16 + 2 * t + 8];
                mma_f16(o[nf], pf, vf);
            }
        }
        __syncthreads();
    }
#undef AFILL

    l0 += __shfl_xor_sync(0xffffffffu, l0, 1);
    l0 += __shfl_xor_sync(0xffffffffu, l0, 2);
    l1 += __shfl_xor_sync(0xffffffffu, l1, 1);
    l1 += __shfl_xor_sync(0xffffffffu, l1, 2);
    float inv0 = 1.f / l0, inv1 = 1.f / l1;
    int gr0 = qt * 128 + w16 + g, gr1 = gr0 + 8;
    #pragma unroll
    for (int nf = 0; nf < 8; nf++) {
        int col = h * HD + nf * 8 + 2 * t;
        if (gr0 < S_TOT)
            *(__half2*)(g_attn + ((size_t)(b * S_TOT + gr0)) * DIM + col) =
                __floats2half2_rn(o[nf][0] * inv0, o[nf][1] * inv0);
        if (gr1 < S_TOT)
            *(__half2*)(g_attn + ((size_t)(b * S_TOT + gr1)) * DIM + col) =
                __floats2half2_rn(o[nf][2] * inv1, o[nf][3] * inv1);
    }
}

// ---------------- launch ----------------
extern "C" void kernel_launch(void* const* d_in, const int* in_sizes, int n_in,
                              void* d_out, int out_size) {
    const float* hidden   = (const float*)d_in[0];
    const float* enc      = (const float*)d_in[1];
    const float* temb     = (const float*)d_in[2];
    const float* rope_cos = (const float*)d_in[3];
    const float* rope_sin = (const float*)d_in[4];
    const float* w_adaln1 = (const float*)d_in[5];
    const float* b_adaln1 = (const float*)d_in[6];
    const float* ln1_g    = (const float*)d_in[7];
    const float* ln1_b    = (const float*)d_in[8];
    const float* wq       = (const float*)d_in[9];
    const float* wk       = (const float*)d_in[10];
    const float* wv       = (const float*)d_in[11];
    const float* wo       = (const float*)d_in[12];
    const float* bo       = (const float*)d_in[13];
    const float* nq_g     = (const float*)d_in[14];
    const float* nq_b     = (const float*)d_in[15];
    const float* nk_g     = (const float*)d_in[16];
    const float* nk_b     = (const float*)d_in[17];
    const float* w_adaln2 = (const float*)d_in[18];
    const float* b_adaln2 = (const float*)d_in[19];
    const float* ln2_g    = (const float*)d_in[20];
    const float* ln2_b    = (const float*)d_in[21];
    const float* w_ff1    = (const float*)d_in[22];
    const float* b_ff1    = (const float*)d_in[23];
    const float* w_ff2    = (const float*)d_in[24];
    const float* b_ff2    = (const float*)d_in[25];

    float* out_h = (float*)d_out;
    float* out_e = out_h + (size_t)BATCH * S_VID * DIM;

    const int N8_W = DIM * DIM / 8;
    const int N8_F = FF_D * DIM / 8;

    // one-time host-side stream/event setup (no device memory involved)
    static cudaStream_t s2 = nullptr;
    static cudaEvent_t evFork = nullptr, evQKV = nullptr, evW = nullptr;
    if (s2 == nullptr) {
        cudaStreamCreateWithFlags(&s2, cudaStreamNonBlocking);
        cudaEventCreateWithFlags(&evFork, cudaEventDisableTiming);
        cudaEventCreateWithFlags(&evQKV, cudaEventDisableTiming);
        cudaEventCreateWithFlags(&evW, cudaEventDisableTiming);
        cudaFuncSetAttribute(attn_kernel, cudaFuncAttributeMaxDynamicSharedMemorySize, ATT_SMEM);
    }

    // ---- fork: weight copies on s2, activation path on default stream ----
    cudaEventRecord(evFork, 0);
    cudaStreamWaitEvent(s2, evFork, 0);

    h_copy<0><<<(N8_W + 255) / 256, 256, 0, s2>>>(wq, 0, N8_W);
    h_copy<0><<<(N8_W + 255) / 256, 256, 0, s2>>>(wk, DIM * DIM, N8_W);
    h_copy<0><<<(N8_W + 255) / 256, 256, 0, s2>>>(wv, 2 * DIM * DIM, N8_W);
    cudaEventRecord(evQKV, s2);
    h_copy<1><<<(N8_W + 255) / 256, 256, 0, s2>>>(wo, 0, N8_W);
    h_copy<2><<<(N8_F + 255) / 256, 256, 0, s2>>>(w_ff1, 0, N8_F);
    h_copy<3><<<(N8_F + 255) / 256, 256, 0, s2>>>(w_ff2, 0, N8_F);
    cudaEventRecord(evW, s2);

    // activation path (overlaps qkv weight copies)
    silu_kernel<<<(BATCH * TEMB_D + 255) / 256, 256>>>(temb);
    mods_kernel<0><<<(BATCH * MODSZ * 32 + 255) / 256, 256>>>(w_adaln1, b_adaln1);
    mods_kernel<1><<<(BATCH * MODSZ * 32 + 255) / 256, 256>>>(w_adaln2, b_adaln2);
    ln_mod_kernel<0><<<M_ROWS, 256>>>(hidden, enc, ln1_g, ln1_b);

    // join 1: need g_wqkv
    cudaStreamWaitEvent(0, evQKV, 0);

    // FUSED QKV projection: one GEMM, N = 9216, fp16 output
    dim3 gqkv(QKV_N / 128, (M_ROWS + 127) / 128);
    hgemm_nt<0, 0, 0, 3, 1, 0><<<gqkv, 128>>>(nullptr, 0, M_ROWS, QKV_N, DIM,
                                              nullptr, nullptr, nullptr, nullptr);

    // V transpose and QK-LN + RoPE (fp16 in/out) — overlaps wo/wf copies
    vtrans_kernel<<<dim3((S_TOT + 63) / 64, BATCH * HEADS), 128>>>();
    qk_post_kernel<<<(BATCH * HEADS * S_TOT * 32) / 128, 128>>>(rope_cos, rope_sin,
                                                                nq_g, nq_b, nk_g, nk_b);

    // fp16 tensor-core flash attention (128-row q tiles)
    attn_kernel<<<dim3((S_TOT + 127) / 128, BATCH * HEADS), 256, ATT_SMEM>>>();

    // join 2: need g_wo / g_wf1 / g_wf2
    cudaStreamWaitEvent(0, evW, 0);

    // output projection with FUSED residual+gate -> d_out
    dim3 g1(DIM / 128, (M_ROWS + 127) / 128);
    hgemm_nt<0, 1, 1, 0, 0, 1><<<g1, 128>>>(bo, 0, M_ROWS, DIM, DIM,
                                            hidden, enc, out_h, out_e);

    // adaLN2 + FF
    ln_mod_kernel<1><<<M_ROWS, 256>>>(out_h, out_e, ln2_g, ln2_b);
    dim3 g2(FF_D / 128, (M_ROWS + 127) / 128);
    hgemm_nt<1, 0, 2, 2, 1, 0><<<g2, 128>>>(b_ff1, 0, M_ROWS, FF_D, DIM,
                                            nullptr, nullptr, nullptr, nullptr);
    // ff2 with FUSED final gated residual (+=)
    hgemm_nt<0, 2, 3, 0, 0, 2><<<g1, 128>>>(b_ff2, 0, M_ROWS, DIM, FF_D,
                                            nullptr, nullptr, out_h, out_e);
}

// round 16
// speedup vs baseline: 1.0103x; 1.0103x over previous
#include <cuda_runtime.h>
#include <cuda_fp16.h>
#include <math.h>

#define DIM    3072
#define HEADS  48
#define HD     64
#define TEMB_D 512
#define BATCH  2
#define T_TXT  226
#define S_VID  1024
#define S_TOT  1250
#define FF_D   12288
#define M_ROWS 2500      // BATCH * S_TOT
#define MODSZ  18432     // 6*DIM
#define BIGN   7680000   // M_ROWS*DIM
#define QKV_N  9216      // 3*DIM
#define VT_STRIDE 1280   // padded key stride for V^T (16B-aligned cp.async)

// ---------------- scratch (static device memory; no allocs) ----------------
__device__ float g_silu[BATCH * TEMB_D];
__device__ float g_mods1[BATCH * MODSZ];
__device__ float g_mods2[BATCH * MODSZ];
__device__ float g_dummyf[2];
__device__ __half g_cat[BIGN];          // cat1/cat2 (fp16)
__device__ __half g_q[BIGN];            // (B,H,S,HD) scaled fp16
__device__ __half g_k[BIGN];            // fp16
__device__ __half g_vT[BATCH * HEADS * HD * VT_STRIDE];  // fp16
__device__ __half g_attn[BIGN];         // attention out (fp16)
__device__ __half g_ff1[M_ROWS * FF_D]; // (fp16)

// fp16 weight copies
__device__ __half g_wqkv[3 * DIM * DIM];   // rows: wq | wk | wv
__device__ __half g_wo[DIM * DIM];
__device__ __half g_wf1[FF_D * DIM];
__device__ __half g_wf2[FF_D * DIM];

template<int ID> __device__ __forceinline__ __half* hbuf();
template<> __device__ __forceinline__ __half* hbuf<0>() { return g_cat; }
template<> __device__ __forceinline__ __half* hbuf<1>() { return g_attn; }
template<> __device__ __forceinline__ __half* hbuf<2>() { return g_ff1; }

template<int ID> __device__ __forceinline__ float* fbuf();
template<> __device__ __forceinline__ float* fbuf<0>() { return g_dummyf; }

template<int ID> __device__ __forceinline__ __half* whbuf();
template<> __device__ __forceinline__ __half* whbuf<0>() { return g_wqkv; }
template<> __device__ __forceinline__ __half* whbuf<1>() { return g_wo; }
template<> __device__ __forceinline__ __half* whbuf<2>() { return g_wf1; }
template<> __device__ __forceinline__ __half* whbuf<3>() { return g_wf2; }

__device__ __forceinline__ float gelu_tanh(float x) {
    float t = tanhf(0.7978845608028654f * (x + 0.044715f * x * x * x));
    return 0.5f * x * (1.0f + t);
}
__device__ __forceinline__ unsigned smem_u32(const void* p) {
    return (unsigned)__cvta_generic_to_shared(p);
}
__device__ __forceinline__ void cp_async16(unsigned dst, const void* src) {
    asm volatile("cp.async.cg.shared.global [%0], [%1], 16;" :: "r"(dst), "l"(src));
}
#define CP_COMMIT() asm volatile("cp.async.commit_group;" ::: "memory")
#define CP_WAIT1()  asm volatile("cp.async.wait_group 1;" ::: "memory")
#define CP_WAIT0()  asm volatile("cp.async.wait_group 0;" ::: "memory")

__device__ __forceinline__ void mma_f16(float* d, const unsigned* a, const unsigned* b) {
    asm volatile(
        "mma.sync.aligned.m16n8k16.row.col.f32.f16.f16.f32 "
        "{%0,%1,%2,%3},{%4,%5,%6,%7},{%8,%9},{%0,%1,%2,%3};"
        : "+f"(d[0]), "+f"(d[1]), "+f"(d[2]), "+f"(d[3])
        : "r"(a[0]), "r"(a[1]), "r"(a[2]), "r"(a[3]), "r"(b[0]), "r"(b[1]));
}

// ---------------- fp16 weight copy ----------------
template<int WID>
__global__ void h_copy(const float* __restrict__ src, int dst_off, int n8) {
    int i = blockIdx.x * blockDim.x + threadIdx.x;
    if (i >= n8) return;
    float4 v0 = ((const float4*)src)[2 * i];
    float4 v1 = ((const float4*)src)[2 * i + 1];
    __half2 h0 = __floats2half2_rn(v0.x, v0.y);
    __half2 h1 = __floats2half2_rn(v0.z, v0.w);
    __half2 h2 = __floats2half2_rn(v1.x, v1.y);
    __half2 h3 = __floats2half2_rn(v1.z, v1.w);
    uint4 out;
    out.x = *(unsigned*)&h0; out.y = *(unsigned*)&h1;
    out.z = *(unsigned*)&h2; out.w = *(unsigned*)&h3;
    ((uint4*)(whbuf<WID>() + dst_off))[i] = out;
}

// ---------------- silu(temb) ----------------
__global__ void silu_kernel(const float* __restrict__ temb) {
    int i = blockIdx.x * blockDim.x + threadIdx.x;
    if (i < BATCH * TEMB_D) {
        float x = temb[i];
        g_silu[i] = x / (1.0f + expf(-x));
    }
}

// ---------------- mods = silu(temb) @ W.T + b ----------------
template<int WHICH>
__global__ void mods_kernel(const float* __restrict__ w, const float* __restrict__ bias) {
    float* out = (WHICH == 0) ? g_mods1 : g_mods2;
    int gw = (blockIdx.x * blockDim.x + threadIdx.x) >> 5;
    int lane = threadIdx.x & 31;
    if (gw >= BATCH * MODSZ) return;
    int b = gw / MODSZ, n = gw % MODSZ;
    const float* wr = w + (size_t)n * TEMB_D;
    const float* sr = g_silu + b * TEMB_D;
    float acc = 0.f;
    #pragma unroll 4
    for (int k = lane; k < TEMB_D; k += 32) acc += wr[k] * sr[k];
    #pragma unroll
    for (int off = 16; off; off >>= 1) acc += __shfl_xor_sync(0xffffffffu, acc, off);
    if (lane == 0) out[gw] = acc + bias[n];
}

// ---------------- LayerNorm + adaLN modulation -> g_cat (fp16) ----------------
template<int WHICH>
__global__ __launch_bounds__(256) void ln_mod_kernel(
    const float* __restrict__ hid, const float* __restrict__ enc,
    const float* __restrict__ gamma, const float* __restrict__ beta) {
    const float* mods = (WHICH == 0) ? g_mods1 : g_mods2;
    int row = blockIdx.x;
    int b = row / S_TOT, s = row % S_TOT;
    const float* src;
    int sh_off;
    if (s < T_TXT) { src = enc + ((size_t)b * T_TXT + s) * DIM; sh_off = 3 * DIM; }
    else           { src = hid + ((size_t)b * S_VID + (s - T_TXT)) * DIM; sh_off = 0; }
    const float* mrow = mods + (size_t)b * MODSZ;
    __shared__ float ws[8], wq[8], stat[2];
    int tid = threadIdx.x;
    int lane = tid & 31, warp = tid >> 5;
    float4 xv[3];
    float sum = 0.f, sq = 0.f;
    #pragma unroll
    for (int c = 0; c < 3; c++) {
        xv[c] = *(const float4*)(src + c * 1024 + tid * 4);
        sum += xv[c].x + xv[c].y + xv[c].z + xv[c].w;
        sq  += xv[c].x * xv[c].x + xv[c].y * xv[c].y
             + xv[c].z * xv[c].z + xv[c].w * xv[c].w;
    }
    #pragma unroll
    for (int off = 16; off; off >>= 1) {
        sum += __shfl_xor_sync(0xffffffffu, sum, off);
        sq  += __shfl_xor_sync(0xffffffffu, sq, off);
    }
    if (lane == 0) { ws[warp] = sum; wq[warp] = sq; }
    __syncthreads();
    if (tid == 0) {
        float ts = 0.f, tq = 0.f;
        #pragma unroll
        for (int i = 0; i < 8; i++) { ts += ws[i]; tq += wq[i]; }
        float mean = ts * (1.f / DIM);
        float var = tq * (1.f / DIM) - mean * mean;
        stat[0] = mean;
        stat[1] = rsqrtf(var + 1e-5f);
    }
    __syncthreads();
    float mean = stat[0], inv = stat[1];
    __half* orow = g_cat + (size_t)row * DIM;
    #pragma unroll
    for (int c = 0; c < 3; c++) {
        int d = c * 1024 + tid * 4;
        float4 gm = *(const float4*)(gamma + d);
        float4 bt = *(const float4*)(beta + d);
        float4 sc = *(const float4*)(mrow + sh_off + DIM + d);
        float4 sh = *(const float4*)(mrow + sh_off + d);
        float y0 = ((xv[c].x - mean) * inv * gm.x + bt.x) * (1.f + sc.x) + sh.x;
        float y1 = ((xv[c].y - mean) * inv * gm.y + bt.y) * (1.f + sc.y) + sh.y;
        float y2 = ((xv[c].z - mean) * inv * gm.z + bt.z) * (1.f + sc.z) + sh.z;
        float y3 = ((xv[c].w - mean) * inv * gm.w + bt.w) * (1.f + sc.w) + sh.w;
        __half2 h01 = __floats2half2_rn(y0, y1);
        __half2 h23 = __floats2half2_rn(y2, y3);
        uint2 pk;
        pk.x = *(unsigned*)&h01; pk.y = *(unsigned*)&h23;
        *(uint2*)(orow + d) = pk;
    }
}

// ======== FP16 GEMM NT, 128x128 CTA, 4 warps of 64x64, BK=32, 2-stage cp.async ========
// EPI=0: plain write. EPI=1: fused resid. EPI=2: fused final_add.
// EPI=3: fused QKV post (per-head QK-LN + RoPE + scale -> g_q/g_k; V -> g_vT transposed).
//        x0=rope_cos, x1=rope_sin, x2=nq_g, x3=nq_b, x4=nk_g, x5=nk_b
template<int ACT, int SRC, int BID, int DST, int OUTH, int EPI>
__global__ __launch_bounds__(128, 2) void hgemm_nt(
    const float* __restrict__ bias, int b_off, int M, int N, int K,
    const float* __restrict__ x0, const float* __restrict__ x1,
    float* __restrict__ out_h, float* __restrict__ out_e,
    const float* __restrict__ x2, const float* __restrict__ x3,
    const float* __restrict__ x4, const float* __restrict__ x5) {
    const __half* A = hbuf<SRC>();
    const __half* Bw = whbuf<BID>() + b_off;
    __shared__ __align__(16) __half As[2][128][40];
    __shared__ __align__(16) __half Bs[2][128][40];
    const int bm = blockIdx.y * 128;
    const int bn = blockIdx.x * 128;
    const int tid = threadIdx.x;
    const int lane = tid & 31;
    const int w = tid >> 5;
    const int wm = (w & 1) * 64;
    const int wn = (w >> 1) * 64;
    const int g = lane >> 2;
    const int t = lane & 3;

    float acc[4][8][4];
    #pragma unroll
    for (int mf = 0; mf < 4; mf++)
        #pragma unroll
        for (int nf = 0; nf < 8; nf++)
            #pragma unroll
            for (int i = 0; i < 4; i++) acc[mf][nf][i] = 0.f;

    const int nch = K >> 5;

#define FILL(j)                                                                 \
    {                                                                           \
        int st_ = (j) & 1;                                                      \
        int k0_ = (j) << 5;                                                     \
        _Pragma("unroll")                                                       \
        for (int i_ = 0; i_ < 4; i_++) {                                        \
            int idx_ = i_ * 128 + tid;                                          \
            int row_ = idx_ >> 2;                                               \
            int c8_ = (idx_ & 3) << 3;                                          \
            int ga_ = bm + row_; if (ga_ >= M) ga_ = M - 1;                     \
            cp_async16(smem_u32(&As[st_][row_][c8_]),                           \
                       A + (size_t)ga_ * K + k0_ + c8_);                        \
            cp_async16(smem_u32(&Bs[st_][row_][c8_]),                           \
                       Bw + (size_t)(bn + row_) * K + k0_ + c8_);               \
        }                                                                       \
        CP_COMMIT();                                                            \
    }

    FILL(0);

    for (int j = 0; j < nch; j++) {
        if (j + 1 < nch) { FILL(j + 1); CP_WAIT1(); } else { CP_WAIT0(); }
        __syncthreads();
        int st = j & 1;
        #pragma unroll
        for (int kk = 0; kk < 32; kk += 16) {
            unsigned af[4][4], bf[8][2];
            #pragma unroll
            for (int mf = 0; mf < 4; mf++) {
                int rb = wm + mf * 16;
                af[mf][0] = *(const unsigned*)&As[st][rb + g][kk + 2 * t];
                af[mf][1] = *(const unsigned*)&As[st][rb + g + 8][kk + 2 * t];
                af[mf][2] = *(const unsigned*)&As[st][rb + g][kk + 2 * t + 8];
                af[mf][3] = *(const unsigned*)&As[st][rb + g + 8][kk + 2 * t + 8];
            }
            #pragma unroll
            for (int nf = 0; nf < 8; nf++) {
                int cb = wn + nf * 8;
                bf[nf][0] = *(const unsigned*)&Bs[st][cb + g][kk + 2 * t];
                bf[nf][1] = *(const unsigned*)&Bs[st][cb + g][kk + 2 * t + 8];
            }
            #pragma unroll
            for (int mf = 0; mf < 4; mf++)
                #pragma unroll
                for (int nf = 0; nf < 8; nf++)
                    mma_f16(acc[mf][nf], af[mf], bf[nf]);
        }
        __syncthreads();
    }
#undef FILL

    if (EPI == 3) {
        // Fused QKV post-processing epilogue.
        const int region = bn / DIM;                       // 0=q, 1=k, 2=v
        const int h = ((bn % DIM) + wn) >> 6;              // head within 48
        #pragma unroll
        for (int mf = 0; mf < 4; mf++) {
            #pragma unroll
            for (int half = 0; half < 2; half++) {
                int r = bm + wm + mf * 16 + g + half * 8;
                bool valid = (r < M);
                int rc = valid ? r : (M - 1);
                int bb_ = rc / S_TOT, ss = rc % S_TOT;
                float vals[16];
                #pragma unroll
                for (int nf = 0; nf < 8; nf++) {
                    vals[2 * nf]     = acc[mf][nf][half * 2];
                    vals[2 * nf + 1] = acc[mf][nf][half * 2 + 1];
                }
                if (region < 2) {
                    float sum = 0.f, sq = 0.f;
                    #pragma unroll
                    for (int i = 0; i < 16; i++) { sum += vals[i]; sq += vals[i] * vals[i]; }
                    sum += __shfl_xor_sync(0xffffffffu, sum, 1);
                    sum += __shfl_xor_sync(0xffffffffu, sum, 2);
                    sq  += __shfl_xor_sync(0xffffffffu, sq, 1);
                    sq  += __shfl_xor_sync(0xffffffffu, sq, 2);
                    float mean = sum * (1.f / HD);
                    float var = sq * (1.f / HD) - mean * mean;
                    float inv = rsqrtf(var + 1e-6f);
                    const float* gg = (region == 0) ? x2 : x4;
                    const float* bv = (region == 0) ? x3 : x5;
                    bool do_rope = (ss >= T_TXT);
                    int ri = ss - T_TXT;
                    __half* dstbase = ((region == 0) ? g_q : g_k)
                                    + ((size_t)(bb_ * HEADS + h) * S_TOT + ss) * HD;
                    #pragma unroll
                    for (int nf = 0; nf < 8; nf++) {
                        int d0 = nf * 8 + 2 * t;
                        float y0 = (vals[2 * nf]     - mean) * inv * gg[d0]     + bv[d0];
                        float y1 = (vals[2 * nf + 1] - mean) * inv * gg[d0 + 1] + bv[d0 + 1];
                        if (do_rope) {
                            float c0 = x0[ri * HD + d0],     s0 = x1[ri * HD + d0];
                            float c1 = x0[ri * HD + d0 + 1], s1 = x1[ri * HD + d0 + 1];
                            float r0 = y0 * c0 - y1 * s0;
                            float r1 = y1 * c1 + y0 * s1;
                            y0 = r0; y1 = r1;
                        }
                        if (region == 0) { y0 *= 0.125f; y1 *= 0.125f; }
                        if (valid)
                            *(__half2*)(dstbase + d0) = __floats2half2_rn(y0, y1);
                    }
                } else {
                    if (valid) {
                        __half* dst = g_vT + (size_t)(bb_ * HEADS + h) * HD * VT_STRIDE;
                        #pragma unroll
                        for (int nf = 0; nf < 8; nf++) {
                            int d0 = nf * 8 + 2 * t;
                            dst[(size_t)d0 * VT_STRIDE + ss]       = __float2half_rn(vals[2 * nf]);
                            dst[(size_t)(d0 + 1) * VT_STRIDE + ss] = __float2half_rn(vals[2 * nf + 1]);
                        }
                    }
                }
            }
        }
        return;
    }

    // generic epilogue
    const float* mods = (EPI == 1) ? g_mods1 : g_mods2;
    #pragma unroll
    for (int mf = 0; mf < 4; mf++) {
        int r0 = bm + wm + mf * 16 + g;
        int r1 = r0 + 8;
        int b0r = 0, s0r = 0, b1r = 0, s1r = 0;
        if (EPI == 1 || EPI == 2) {
            b0r = r0 / S_TOT; s0r = r0 % S_TOT;
            b1r = r1 / S_TOT; s1r = r1 % S_TOT;
        }
        #pragma unroll
        for (int nf = 0; nf < 8; nf++) {
            int col = bn + wn + nf * 8 + 2 * t;
            float bb0 = bias ? bias[col] : 0.f;
            float bb1 = bias ? bias[col + 1] : 0.f;
            float v0 = acc[mf][nf][0] + bb0;
            float v1 = acc[mf][nf][1] + bb1;
            float v2 = acc[mf][nf][2] + bb0;
            float v3 = acc[mf][nf][3] + bb1;
            if (ACT == 1) {
                v0 = gelu_tanh(v0); v1 = gelu_tanh(v1);
                v2 = gelu_tanh(v2); v3 = gelu_tanh(v3);
            }
            if (EPI == 0) {
                if (OUTH == 1) {
                    __half* C = hbuf<DST>();
                    __half2 h01 = __floats2half2_rn(v0, v1);
                    __half2 h23 = __floats2half2_rn(v2, v3);
                    if (r0 < M) *(__half2*)(C + (size_t)r0 * N + col) = h01;
                    if (r1 < M) *(__half2*)(C + (size_t)r1 * N + col) = h23;
                } else {
                    float* C = fbuf<DST>();
                    if (r0 < M) *(float2*)(C + (size_t)r0 * N + col) = make_float2(v0, v1);
                    if (r1 < M) *(float2*)(C + (size_t)r1 * N + col) = make_float2(v2, v3);
                }
            } else {
                #pragma unroll
                for (int half = 0; half < 2; half++) {
                    int r = half ? r1 : r0;
                    if (r >= M) continue;
                    int bb = half ? b1r : b0r;
                    int ss = half ? s1r : s0r;
                    float va = half ? v2 : v0;
                    float vb = half ? v3 : v1;
                    if (ss < T_TXT) {
                        float ga = mods[bb * MODSZ + 5 * DIM + col];
                        float gb = mods[bb * MODSZ + 5 * DIM + col + 1];
                        size_t idx = ((size_t)bb * T_TXT + ss) * DIM + col;
                        if (EPI == 1) {
                            float2 e = *(const float2*)(x1 + idx);
                            *(float2*)(out_e + idx) = make_float2(e.x + ga * va, e.y + gb * vb);
                        } else {
                            float2 e = *(const float2*)(out_e + idx);
                            *(float2*)(out_e + idx) = make_float2(e.x + ga * va, e.y + gb * vb);
                        }
                    } else {
                        float ga = mods[bb * MODSZ + 2 * DIM + col];
                        float gb = mods[bb * MODSZ + 2 * DIM + col + 1];
                        size_t idx = ((size_t)bb * S_VID + (ss - T_TXT)) * DIM + col;
                        if (EPI == 1) {
                            float2 hh = *(const float2*)(x0 + idx);
                            *(float2*)(out_h + idx) = make_float2(hh.x + ga * va, hh.y + gb * vb);
                        } else {
                            float2 hh = *(const float2*)(out_h + idx);
                            *(float2*)(out_h + idx) = make_float2(hh.x + ga * va, hh.y + gb * vb);
                        }
                    }
                }
            }
        }
    }
}

// ---------------- fp16 tensor-core flash attention (64-row q tile) ----------------
#define HST 72
#define ATT_SMEM (5 * 64 * HST * 2)

__global__ __launch_bounds__(128, 2) void attn_kernel() {
    extern __shared__ __half hsm[];
    __half (*QPs)[HST] = (__half(*)[HST])hsm;
    __half (*Ksm)[HST] = (__half(*)[HST])(hsm + 64 * HST);
    __half (*Vsm)[HST] = (__half(*)[HST])(hsm + 3 * 64 * HST);
    const int qt = blockIdx.x;
    const int bh = blockIdx.y;
    const int b = bh / HEADS, h = bh % HEADS;
    const __half* Qb = g_q + (size_t)bh * S_TOT * HD;
    const __half* Kb = g_k + (size_t)bh * S_TOT * HD;
    const __half* Vb = g_vT + (size_t)bh * HD * VT_STRIDE;
    const int tid = threadIdx.x;
    const int w = tid >> 5, lane = tid & 31;
    const int g = lane >> 2, t = lane & 3;
    const int w16 = w * 16;
    const int NKT = (S_TOT + 63) / 64;
    const int LASTV = S_TOT - (NKT - 1) * 64;

    #pragma unroll
    for (int i = 0; i < 4; i++) {
        int idx = i * 128 + tid;
        int r = idx >> 3, c8 = (idx & 7) << 3;
        int qr = qt * 64 + r; if (qr >= S_TOT) qr = S_TOT - 1;
        cp_async16(smem_u32(&QPs[r][c8]), Qb + (size_t)qr * HD + c8);
    }
    CP_COMMIT();

#define AFILL(kt_)                                                                \
    {                                                                             \
        int st_ = (kt_) & 1;                                                      \
        _Pragma("unroll")                                                         \
        for (int i_ = 0; i_ < 4; i_++) {                                          \
            int idx_ = i_ * 128 + tid;                                            \
            int r_ = idx_ >> 3, c8_ = (idx_ & 7) << 3;                            \
            int key_ = (kt_) * 64 + r_; if (key_ >= S_TOT) key_ = S_TOT - 1;      \
            cp_async16(smem_u32(&Ksm[st_ * 64 + r_][c8_]),                        \
                       Kb + (size_t)key_ * HD + c8_);                             \
            cp_async16(smem_u32(&Vsm[st_ * 64 + r_][c8_]),                        \
                       Vb + (size_t)r_ * VT_STRIDE + (kt_) * 64 + c8_);           \
        }                                                                         \
        CP_COMMIT();                                                              \
    }

    AFILL(0);

    unsigned qf[4][4];
    float o[8][4];
    #pragma unroll
    for (int nf = 0; nf < 8; nf++)
        #pragma unroll
        for (int i = 0; i < 4; i++) o[nf][i] = 0.f;
    float m0 = -1e30f, m1 = -1e30f, l0 = 0.f, l1 = 0.f;

    for (int kt = 0; kt < NKT; kt++) {
        if (kt + 1 < NKT) { AFILL(kt + 1); CP_WAIT1(); } else { CP_WAIT0(); }
        __syncthreads();
        if (kt == 0) {
            #pragma unroll
            for (int ks = 0; ks < 4; ks++) {
                qf[ks][0] = *(const unsigned*)&QPs[w16 + g][ks * 16 + 2 * t];
                qf[ks][1] = *(const unsigned*)&QPs[w16 + g + 8][ks * 16 + 2 * t];
                qf[ks][2] = *(const unsigned*)&QPs[w16 + g][ks * 16 + 2 * t + 8];
                qf[ks][3] = *(const unsigned*)&QPs[w16 + g + 8][ks * 16 + 2 * t + 8];
            }
            __syncthreads();
        }
        const __half (*Kst)[HST] = Ksm + (kt & 1) * 64;
        const __half (*Vst)[HST] = Vsm + (kt & 1) * 64;

        float s[8][4];
        #pragma unroll
        for (int nf = 0; nf < 8; nf++)
            #pragma unroll
            for (int i = 0; i < 4; i++) s[nf][i] = 0.f;
        #pragma unroll
        for (int ks = 0; ks < 4; ks++) {
            #pragma unroll
            for (int nf = 0; nf < 8; nf++) {
                unsigned bfr[2];
                bfr[0] = *(const unsigned*)&Kst[nf * 8 + g][ks * 16 + 2 * t];
                bfr[1] = *(const unsigned*)&Kst[nf * 8 + g][ks * 16 + 2 * t + 8];
                mma_f16(s[nf], qf[ks], bfr);
            }
        }
        if (kt == NKT - 1) {
            #pragma unroll
            for (int nf = 0; nf < 8; nf++) {
                int c0 = nf * 8 + 2 * t;
                if (c0 >= LASTV)     { s[nf][0] = -1e30f; s[nf][2] = -1e30f; }
                if (c0 + 1 >= LASTV) { s[nf][1] = -1e30f; s[nf][3] = -1e30f; }
            }
        }
        float tm0 = -1e30f, tm1 = -1e30f;
        #pragma unroll
        for (int nf = 0; nf < 8; nf++) {
            tm0 = fmaxf(tm0, fmaxf(s[nf][0], s[nf][1]));
            tm1 = fmaxf(tm1, fmaxf(s[nf][2], s[nf][3]));
        }
        tm0 = fmaxf(tm0, __shfl_xor_sync(0xffffffffu, tm0, 1));
        tm0 = fmaxf(tm0, __shfl_xor_sync(0xffffffffu, tm0, 2));
        tm1 = fmaxf(tm1, __shfl_xor_sync(0xffffffffu, tm1, 1));
        tm1 = fmaxf(tm1, __shfl_xor_sync(0xffffffffu, tm1, 2));
        float mn0 = fmaxf(m0, tm0), mn1 = fmaxf(m1, tm1);
        float sc0 = __expf(m0 - mn0), sc1 = __expf(m1 - mn1);
        float ls0 = 0.f, ls1 = 0.f;
        #pragma unroll
        for (int nf = 0; nf < 8; nf++) {
            float p0 = __expf(s[nf][0] - mn0);
            float p1 = __expf(s[nf][1] - mn0);
            float p2 = __expf(s[nf][2] - mn1);
            float p3 = __expf(s[nf][3] - mn1);
            __half2 h01 = __floats2half2_rn(p0, p1);
            __half2 h23 = __floats2half2_rn(p2, p3);
            float2 f01 = __half22float2(h01);
            float2 f23 = __half22float2(h23);
            ls0 += f01.x + f01.y; ls1 += f23.x + f23.y;
            *(__half2*)&QPs[w16 + g][nf * 8 + 2 * t]     = h01;
            *(__half2*)&QPs[w16 + g + 8][nf * 8 + 2 * t] = h23;
        }
        l0 = l0 * sc0 + ls0;
        l1 = l1 * sc1 + ls1;
        m0 = mn0; m1 = mn1;
        #pragma unroll
        for (int nf = 0; nf < 8; nf++) {
            o[nf][0] *= sc0; o[nf][1] *= sc0;
            o[nf][2] *= sc1; o[nf][3] *= sc1;
        }
        __syncwarp();
        #pragma unroll
        for (int ks = 0; ks < 4; ks++) {
            unsigned pf[4];
            pf[0] = *(const unsigned*)&QPs[w16 + g][ks * 16 + 2 * t];
            pf[1] = *(const unsigned*)&QPs[w16 + g + 8][ks * 16 + 2 * t];
            pf[2] = *(const unsigned*)&QPs[w16 + g][ks * 16 + 2 * t + 8];
            pf[3] = *(const unsigned*)&QPs[w16 + g + 8][ks * 16 + 2 * t + 8];
            #pragma unroll
            for (int nf = 0; nf < 8; nf++) {
                unsigned vf[2];
                vf[0] = *(const unsigned*)&Vst[nf * 8 + g][ks * 16 + 2 * t];
                vf[1] = *(const unsigned*)&Vst[nf * 8 + g][ks * 16 + 2 * t + 8];
                mma_f16(o[nf], pf, vf);
            }
        }
        __syncthreads();
    }
#undef AFILL

    l0 += __shfl_xor_sync(0xffffffffu, l0, 1);
    l0 += __shfl_xor_sync(0xffffffffu, l0, 2);
    l1 += __shfl_xor_sync(0xffffffffu, l1, 1);
    l1 += __shfl_xor_sync(0xffffffffu, l1, 2);
    float inv0 = 1.f / l0, inv1 = 1.f / l1;
    int gr0 = qt * 64 + w16 + g, gr1 = gr0 + 8;
    #pragma unroll
    for (int nf = 0; nf < 8; nf++) {
        int col = h * HD + nf * 8 + 2 * t;
        if (gr0 < S_TOT)
            *(__half2*)(g_attn + ((size_t)(b * S_TOT + gr0)) * DIM + col) =
                __floats2half2_rn(o[nf][0] * inv0, o[nf][1] * inv0);
        if (gr1 < S_TOT)
            *(__half2*)(g_attn + ((size_t)(b * S_TOT + gr1)) * DIM + col) =
                __floats2half2_rn(o[nf][2] * inv1, o[nf][3] * inv1);
    }
}

// ---------------- launch ----------------
extern "C" void kernel_launch(void* const* d_in, const int* in_sizes, int n_in,
                              void* d_out, int out_size) {
    const float* hidden   = (const float*)d_in[0];
    const float* enc      = (const float*)d_in[1];
    const float* temb     = (const float*)d_in[2];
    const float* rope_cos = (const float*)d_in[3];
    const float* rope_sin = (const float*)d_in[4];
    const float* w_adaln1 = (const float*)d_in[5];
    const float* b_adaln1 = (const float*)d_in[6];
    const float* ln1_g    = (const float*)d_in[7];
    const float* ln1_b    = (const float*)d_in[8];
    const float* wq       = (const float*)d_in[9];
    const float* wk       = (const float*)d_in[10];
    const float* wv       = (const float*)d_in[11];
    const float* wo       = (const float*)d_in[12];
    const float* bo       = (const float*)d_in[13];
    const float* nq_g     = (const float*)d_in[14];
    const float* nq_b     = (const float*)d_in[15];
    const float* nk_g     = (const float*)d_in[16];
    const float* nk_b     = (const float*)d_in[17];
    const float* w_adaln2 = (const float*)d_in[18];
    const float* b_adaln2 = (const float*)d_in[19];
    const float* ln2_g    = (const float*)d_in[20];
    const float* ln2_b    = (const float*)d_in[21];
    const float* w_ff1    = (const float*)d_in[22];
    const float* b_ff1    = (const float*)d_in[23];
    const float* w_ff2    = (const float*)d_in[24];
    const float* b_ff2    = (const float*)d_in[25];

    float* out_h = (float*)d_out;
    float* out_e = out_h + (size_t)BATCH * S_VID * DIM;

    const int N8_W = DIM * DIM / 8;
    const int N8_F = FF_D * DIM / 8;

    // one-time host-side stream/event setup (no device memory involved)
    static cudaStream_t s2 = nullptr;
    static cudaEvent_t evFork = nullptr, evQKV = nullptr, evW = nullptr;
    if (s2 == nullptr) {
        cudaStreamCreateWithFlags(&s2, cudaStreamNonBlocking);
        cudaEventCreateWithFlags(&evFork, cudaEventDisableTiming);
        cudaEventCreateWithFlags(&evQKV, cudaEventDisableTiming);
        cudaEventCreateWithFlags(&evW, cudaEventDisableTiming);
        cudaFuncSetAttribute(attn_kernel, cudaFuncAttributeMaxDynamicSharedMemorySize, ATT_SMEM);
    }

    // ---- fork: weight copies on s2, activation path on default stream ----
    cudaEventRecord(evFork, 0);
    cudaStreamWaitEvent(s2, evFork, 0);

    h_copy<0><<<(N8_W + 255) / 256, 256, 0, s2>>>(wq, 0, N8_W);
    h_copy<0><<<(N8_W + 255) / 256, 256, 0, s2>>>(wk, DIM * DIM, N8_W);
    h_copy<0><<<(N8_W + 255) / 256, 256, 0, s2>>>(wv, 2 * DIM * DIM, N8_W);
    cudaEventRecord(evQKV, s2);
    h_copy<1><<<(N8_W + 255) / 256, 256, 0, s2>>>(wo, 0, N8_W);
    h_copy<2><<<(N8_F + 255) / 256, 256, 0, s2>>>(w_ff1, 0, N8_F);
    h_copy<3><<<(N8_F + 255) / 256, 256, 0, s2>>>(w_ff2, 0, N8_F);
    cudaEventRecord(evW, s2);

    // activation path (overlaps qkv weight copies)
    silu_kernel<<<(BATCH * TEMB_D + 255) / 256, 256>>>(temb);
    mods_kernel<0><<<(BATCH * MODSZ * 32 + 255) / 256, 256>>>(w_adaln1, b_adaln1);
    mods_kernel<1><<<(BATCH * MODSZ * 32 + 255) / 256, 256>>>(w_adaln2, b_adaln2);
    ln_mod_kernel<0><<<M_ROWS, 256>>>(hidden, enc, ln1_g, ln1_b);

    // join 1: need g_wqkv
    cudaStreamWaitEvent(0, evQKV, 0);

    // FUSED QKV projection + QK-LN/RoPE + V-transpose epilogue
    dim3 gqkv(QKV_N / 128, (M_ROWS + 127) / 128);
    hgemm_nt<0, 0, 0, 0, 0, 3><<<gqkv, 128>>>(nullptr, 0, M_ROWS, QKV_N, DIM,
                                              rope_cos, rope_sin, nullptr, nullptr,
                                              nq_g, nq_b, nk_g, nk_b);

    // fp16 tensor-core flash attention (64-row q tiles)
    attn_kernel<<<dim3((S_TOT + 63) / 64, BATCH * HEADS), 128, ATT_SMEM>>>();

    // join 2: need g_wo / g_wf1 / g_wf2
    cudaStreamWaitEvent(0, evW, 0);

    // output projection with FUSED residual+gate -> d_out
    dim3 g1(DIM / 128, (M_ROWS + 127) / 128);
    hgemm_nt<0, 1, 1, 0, 0, 1><<<g1, 128>>>(bo, 0, M_ROWS, DIM, DIM,
                                            hidden, enc, out_h, out_e,
                                            nullptr, nullptr, nullptr, nullptr);

    // adaLN2 + FF
    ln_mod_kernel<1><<<M_ROWS, 256>>>(out_h, out_e, ln2_g, ln2_b);
    dim3 g2(FF_D / 128, (M_ROWS + 127) / 128);
    hgemm_nt<1, 0, 2, 2, 1, 0><<<g2, 128>>>(b_ff1, 0, M_ROWS, FF_D, DIM,
                                            nullptr, nullptr, nullptr, nullptr,
                                            nullptr, nullptr, nullptr, nullptr);
    // ff2 with FUSED final gated residual (+=)
    hgemm_nt<0, 2, 3, 0, 0, 2><<<g1, 128>>>(b_ff2, 0, M_ROWS, DIM, FF_D,
                                            nullptr, nullptr, out_h, out_e,
                                            nullptr, nullptr, nullptr, nullptr);
}